// round 8
// baseline (speedup 1.0000x reference)
#include <cuda_runtime.h>
#include <cuda_fp16.h>
#include <cstdint>
#include <math.h>

// ---------------- config ----------------
#define BATCH   16
#define SEQ     2048
#define NCH     64
#define DMODEL  256
#define DINNER  512
#define DSTATE  64
#define NHEADS  8
#define HP      64
#define CONVDIM 640          // DINNER + 2*DSTATE
#define DPROJ   1160         // 2*DINNER + 2*DSTATE + NHEADS
#define NROWS   (BATCH*SEQ)  // 32768
#define NLAYERS 4
#define LN_EPS  1e-5f
#define DPROJP  1280         // DPROJ padded to 128
#define TCH     32           // conv time-chunk

// ---------------- scratch (device globals; allocation-free) ----------------
__device__ float  g_h[NROWS*DMODEL];        // residual stream (fp32)
__device__ __half g_hh[NROWS*DMODEL];       // fp16 copy of h
__device__ __half g_zxh[NROWS*DPROJ];       // zxbcdt (fp16)
__device__ __half g_xacth[NROWS*DINNER];    // silu(conv(x))+b (fp16, x part only)
__device__ float  g_bcf[NROWS*2*DSTATE];    // conv'd B,C (fp32, packed pairs)
__device__ float2 g_dtA[NROWS*NHEADS];      // (softplus dt, exp(dt*A)) fp32
__device__ __half g_ysc[NROWS*DINNER];      // scan output y (fp16, final)
__device__ __half g_mh[NROWS*DMODEL];       // y @ W_out (fp16)

// fp16 activations (GEMM A operands)
__device__ __half g_xh[NROWS*NCH];
__device__ __half g_yh[NROWS*DINNER];

// fp16 transposed weights (GEMM B operands), [Npad][K]
__device__ __half g_linw[DMODEL*NCH];
__device__ __half g_winw[NLAYERS*DPROJP*DMODEL];
__device__ __half g_woutw[NLAYERS*DMODEL*DINNER];

__device__ __forceinline__ float siluf(float x) {
    return x * (1.f / (1.f + __expf(-x)));
}

__device__ __forceinline__ uint32_t smem_u32(const void* p) {
    uint32_t a;
    asm("{ .reg .u64 t; cvta.to.shared.u64 t, %1; cvt.u32.u64 %0, t; }"
        : "=r"(a) : "l"(p));
    return a;
}

// ---- packed fp32x2 helpers (sm_100+ family feature; baseline PTX ok) ----
__device__ __forceinline__ unsigned long long f2x_mul(
    unsigned long long a, unsigned long long b) {
    unsigned long long r;
    asm("mul.rn.f32x2 %0, %1, %2;" : "=l"(r) : "l"(a), "l"(b));
    return r;
}
__device__ __forceinline__ unsigned long long f2x_fma(
    unsigned long long a, unsigned long long b, unsigned long long c) {
    unsigned long long r;
    asm("fma.rn.f32x2 %0, %1, %2, %3;" : "=l"(r) : "l"(a), "l"(b), "l"(c));
    return r;
}
__device__ __forceinline__ unsigned long long f2x_pack(float lo, float hi) {
    unsigned long long r;
    asm("mov.b64 %0, {%1, %2};" : "=l"(r) : "f"(lo), "f"(hi));
    return r;
}
__device__ __forceinline__ float2 f2x_unpack(unsigned long long v) {
    float2 o;
    asm("mov.b64 {%0, %1}, %2;" : "=f"(o.x), "=f"(o.y) : "l"(v));
    return o;
}

#define LDM_X4(r0, r1, r2, r3, addr) \
    asm volatile("ldmatrix.sync.aligned.m8n8.x4.shared.b16 {%0,%1,%2,%3}, [%4];" \
        : "=r"(r0), "=r"(r1), "=r"(r2), "=r"(r3) : "r"(addr))

#define MMA_FP16(c, a, b0v, b1v) \
    asm volatile("mma.sync.aligned.m16n8k16.row.col.f32.f16.f16.f32 " \
        "{%0,%1,%2,%3}, {%4,%5,%6,%7}, {%8,%9}, {%0,%1,%2,%3};" \
        : "+f"((c)[0]), "+f"((c)[1]), "+f"((c)[2]), "+f"((c)[3]) \
        : "r"((a)[0]), "r"((a)[1]), "r"((a)[2]), "r"((a)[3]), \
          "r"(b0v), "r"(b1v))

#define CP16(dst, src) \
    asm volatile("cp.async.cg.shared.global [%0], [%1], 16;" \
        :: "r"(dst), "l"(src) : "memory")
#define CPCOMMIT() asm volatile("cp.async.commit_group;" ::: "memory")
#define CPWAIT(n)  asm volatile("cp.async.wait_group %0;" :: "n"(n) : "memory")

// ---------------- weight / input conversion ----------------
__global__ void k_cvt_w(const float* __restrict__ src, __half* __restrict__ dh,
                        int K, int N, int srcStrideLayer, int dstStrideLayer)
{
    int n = blockIdx.x;
    int l = blockIdx.y;
    int k = threadIdx.x;                 // blockDim.x == K
    float v = (n < N) ? src[(size_t)l*srcStrideLayer + (size_t)k*N + n] : 0.f;
    dh[(size_t)l*dstStrideLayer + (size_t)n*K + k] = __float2half_rn(v);
}

__global__ void k_cvt_x(const float* __restrict__ src, __half* __restrict__ d)
{
    int i = blockIdx.x * 256 + threadIdx.x;
    d[i] = __float2half_rn(src[i]);
}

// ============================================================================
// Single-pass fp16 tensor-core GEMM (same as round 7)
// ============================================================================
#define GSTRIDE 40
#define TILEB   (128*GSTRIDE*2)
#define STAGEB  (2*TILEB)
#define GT_SMEM (2*STAGEB)

__global__ __launch_bounds__(256, 2) void k_gemm_fp16(
    const __half* __restrict__ A, const __half* __restrict__ B,
    const float* __restrict__ bias, float* __restrict__ C,
    __half* __restrict__ Ch, int N, int K)
{
    extern __shared__ __align__(128) uint8_t dsm[];
    const uint32_t smb = smem_u32(dsm);

    int tid = threadIdx.x;
    int wid = tid >> 5, lane = tid & 31;
    int m0 = blockIdx.y * 128, n0 = blockIdx.x * 128;
    int wm = wid & 3, wn = wid >> 2;

    float acc[2][8][4];
#pragma unroll
    for (int mt = 0; mt < 2; mt++)
#pragma unroll
        for (int nt = 0; nt < 8; nt++)
#pragma unroll
            for (int j = 0; j < 4; j++) acc[mt][nt][j] = 0.f;

    const __half* srcs[2] = { A + (size_t)m0 * K, B + (size_t)n0 * K };
    const int row0 = tid >> 2, part = tid & 3;

    const uint32_t aoff = (uint32_t)((wm*32 + (lane & 7) + ((lane >> 3) & 1) * 8) * (GSTRIDE*2))
                        + ((lane >> 4) & 1) * 16;
    const uint32_t boff = (uint32_t)((wn*64 + (lane & 7) + ((lane >> 4) & 1) * 8) * (GSTRIDE*2))
                        + ((lane >> 3) & 1) * 16;

    const int NC = K >> 5;

#pragma unroll
    for (int t = 0; t < 2; t++) {
#pragma unroll
        for (int it = 0; it < 2; it++) {
            int r = row0 + it * 64;
            uint32_t d = smb + t * TILEB + (uint32_t)(r * (GSTRIDE*2) + part * 16);
            CP16(d, srcs[t] + (size_t)r * K + part * 8);
        }
    }
    CPCOMMIT();

    for (int c = 0; c < NC; c++) {
        int s = c & 1;
        if (c + 1 < NC) {
            uint32_t sb2 = smb + ((c + 1) & 1) * STAGEB;
            int kb = (c + 1) * 32;
#pragma unroll
            for (int t = 0; t < 2; t++) {
#pragma unroll
                for (int it = 0; it < 2; it++) {
                    int r = row0 + it * 64;
                    uint32_t d = sb2 + t * TILEB + (uint32_t)(r * (GSTRIDE*2) + part * 16);
                    CP16(d, srcs[t] + (size_t)r * K + kb + part * 8);
                }
            }
            CPCOMMIT();
            CPWAIT(1);
        } else {
            CPWAIT(0);
        }
        __syncthreads();

        uint32_t sbase = smb + s * STAGEB;
#pragma unroll
        for (int ks = 0; ks < 2; ks++) {
            uint32_t abase = sbase + aoff + ks * 32;
            uint32_t ra[2][4];
            LDM_X4(ra[0][0], ra[0][1], ra[0][2], ra[0][3], abase);
            LDM_X4(ra[1][0], ra[1][1], ra[1][2], ra[1][3],
                   abase + 16 * (GSTRIDE*2));
            uint32_t rb[8][2];
            uint32_t bbase = sbase + TILEB + boff + ks * 32;
#pragma unroll
            for (int g = 0; g < 4; g++)
                LDM_X4(rb[2*g][0], rb[2*g][1], rb[2*g+1][0], rb[2*g+1][1],
                       bbase + g * 16 * (GSTRIDE*2));
#pragma unroll
            for (int mt = 0; mt < 2; mt++)
#pragma unroll
                for (int nt = 0; nt < 8; nt++)
                    MMA_FP16(acc[mt][nt], ra[mt], rb[nt][0], rb[nt][1]);
        }
        __syncthreads();
    }

    const int gid = lane >> 2, tig = lane & 3;
#pragma unroll
    for (int mt = 0; mt < 2; mt++) {
#pragma unroll
        for (int nt = 0; nt < 8; nt++) {
            int col = n0 + wn * 64 + nt * 8 + tig * 2;
            if (col < N) {
                int r0 = m0 + wm * 32 + mt * 16 + gid;
                float2 v0 = make_float2(acc[mt][nt][0], acc[mt][nt][1]);
                float2 v1 = make_float2(acc[mt][nt][2], acc[mt][nt][3]);
                if (bias) {
                    float b0 = bias[col], b1 = bias[col + 1];
                    v0.x += b0; v0.y += b1; v1.x += b0; v1.y += b1;
                }
                if (C) {
                    *(float2*)(C + (size_t)r0 * N + col) = v0;
                    *(float2*)(C + (size_t)(r0 + 8) * N + col) = v1;
                }
                if (Ch) {
                    *(__half2*)(Ch + (size_t)r0 * N + col) =
                        __floats2half2_rn(v0.x, v0.y);
                    *(__half2*)(Ch + (size_t)(r0 + 8) * N + col) =
                        __floats2half2_rn(v1.x, v1.y);
                }
            }
        }
    }
}

// ------------- causal depthwise conv(4) + SiLU + dt/dA, t-chunked -------------
// x channels (0..511) -> g_xacth fp16; B/C channels (512..639) -> g_bcf fp32.
__global__ __launch_bounds__(CONVDIM) void k_conv_dt(
    const float* __restrict__ conv_w, const float* __restrict__ conv_b,
    const float* __restrict__ dt_bias, const float* __restrict__ A_log,
    int layer)
{
    int t0 = blockIdx.x * TCH;
    int b  = blockIdx.y;
    int c  = threadIdx.x;                  // 0..639

    const float* wr = conv_w + (size_t)layer*CONVDIM*4 + c*4;
    float w0 = wr[0], w1 = wr[1], w2 = wr[2], w3 = wr[3];
    float cb = conv_b[layer*CONVDIM + c];

    const __half* zc = g_zxh + (size_t)(b*SEQ)*DPROJ + DINNER + c;
    float h3 = 0.f, h2 = 0.f, h1 = 0.f;
    if (t0 >= 3) {
        h3 = __half2float(zc[(size_t)(t0-3)*DPROJ]);
        h2 = __half2float(zc[(size_t)(t0-2)*DPROJ]);
        h1 = __half2float(zc[(size_t)(t0-1)*DPROJ]);
    }

    float dtb = 0.f, Aneg = 0.f;
    const __half* dz = nullptr;
    if (c < NHEADS) {
        dtb  = dt_bias[layer*NHEADS + c];
        Aneg = -expf(A_log[layer*NHEADS + c]);
        dz   = g_zxh + (size_t)(b*SEQ)*DPROJ + DINNER + CONVDIM + c;
    }

    bool isx = (c < DINNER);
    __half* xo = g_xacth + (size_t)(b*SEQ + t0)*DINNER + c;
    float*  bo = g_bcf   + (size_t)(b*SEQ + t0)*(2*DSTATE) + (c - DINNER);

#pragma unroll 4
    for (int u = 0; u < TCH; u++) {
        float cur = __half2float(zc[(size_t)(t0+u)*DPROJ]);
        float s = cb + h3*w0 + h2*w1 + h1*w2 + cur*w3;
        float act = siluf(s);
        if (isx) xo[(size_t)u*DINNER] = __float2half_rn(act);
        else     bo[(size_t)u*(2*DSTATE)] = act;
        h3 = h2; h2 = h1; h1 = cur;
        if (c < NHEADS) {
            float draw = __half2float(dz[(size_t)(t0+u)*DPROJ]) + dtb;
            float dtv = (draw > 20.f) ? draw : log1pf(expf(draw));
            g_dtA[(size_t)(b*SEQ + t0 + u)*NHEADS + c] =
                make_float2(dtv, expf(dtv * Aneg));
        }
    }
}

// ---------------- sequential selective scan, packed f32x2 ----------------
// grid = 128 (b*8+h), block = 512: p = tid>>3 (0..63), q = tid&7 (8 n-slices
// of 8). State 8 fp32 = 4 f32x2 per thread. B/C read pre-packed from g_bcf.
// Writes final y (with D skip) as fp16 to g_ysc.
__global__ __launch_bounds__(512, 1) void k_scan(
    const float* __restrict__ Dp, int layer)
{
    int b = blockIdx.x >> 3, h = blockIdx.x & 7;
    int tid = threadIdx.x;
    int p = tid >> 3, q = tid & 7;
    int n0 = q * 8;

    unsigned long long S2[4];
#pragma unroll
    for (int j = 0; j < 4; j++) S2[j] = f2x_pack(0.f, 0.f);

    float Dh = Dp[layer*NHEADS + h];

    const __half*  xrow = g_xacth + (size_t)(b*SEQ)*DINNER + h*HP + p;
    const float2*  dap  = g_dtA   + (size_t)(b*SEQ)*NHEADS + h;
    const float*   bcb  = g_bcf   + (size_t)(b*SEQ)*(2*DSTATE);
    __half* yp = g_ysc + (size_t)(b*SEQ)*DINNER + h*HP + p;

    // 4-deep prefetch
    float sx[4]; float2 sda[4];
    ulonglong2 sB[4][2], sC[4][2];
#pragma unroll
    for (int u = 0; u < 4; u++) {
        sx[u]  = __half2float(xrow[(size_t)u*DINNER]);
        sda[u] = dap[u*NHEADS];
        const ulonglong2* bp = (const ulonglong2*)(bcb + (size_t)u*(2*DSTATE) + n0);
        const ulonglong2* cp = (const ulonglong2*)(bcb + (size_t)u*(2*DSTATE) + DSTATE + n0);
        sB[u][0] = bp[0]; sB[u][1] = bp[1];
        sC[u][0] = cp[0]; sC[u][1] = cp[1];
    }

    for (int t = 0; t < SEQ; t += 4) {
#pragma unroll
        for (int u = 0; u < 4; u++) {
            float xv = sx[u];
            float2 da = sda[u];
            float coef = da.x * xv;
            unsigned long long dA2 = f2x_pack(da.y, da.y);
            unsigned long long cf2 = f2x_pack(coef, coef);

            unsigned long long b0 = sB[u][0].x, b1 = sB[u][0].y,
                               b2 = sB[u][1].x, b3 = sB[u][1].y;
            unsigned long long c0 = sC[u][0].x, c1 = sC[u][0].y,
                               c2 = sC[u][1].x, c3 = sC[u][1].y;

            S2[0] = f2x_fma(S2[0], dA2, f2x_mul(cf2, b0));
            unsigned long long acc2 = f2x_mul(S2[0], c0);
            S2[1] = f2x_fma(S2[1], dA2, f2x_mul(cf2, b1));
            acc2 = f2x_fma(S2[1], c1, acc2);
            S2[2] = f2x_fma(S2[2], dA2, f2x_mul(cf2, b2));
            acc2 = f2x_fma(S2[2], c2, acc2);
            S2[3] = f2x_fma(S2[3], dA2, f2x_mul(cf2, b3));
            acc2 = f2x_fma(S2[3], c3, acc2);

            float2 av = f2x_unpack(acc2);
            float acc = av.x + av.y;
            acc += __shfl_xor_sync(0xffffffffu, acc, 1);
            acc += __shfl_xor_sync(0xffffffffu, acc, 2);
            acc += __shfl_xor_sync(0xffffffffu, acc, 4);
            if (q == 0)
                yp[(size_t)(t+u)*DINNER] = __float2half_rn(acc + Dh*xv);

            // prefetch t+u+4 into slot u
            int tt = t + u + 4; if (tt > SEQ - 1) tt = SEQ - 1;
            sx[u]  = __half2float(xrow[(size_t)tt*DINNER]);
            sda[u] = dap[tt*NHEADS];
            const ulonglong2* bp = (const ulonglong2*)(bcb + (size_t)tt*(2*DSTATE) + n0);
            const ulonglong2* cp = (const ulonglong2*)(bcb + (size_t)tt*(2*DSTATE) + DSTATE + n0);
            sB[u][0] = bp[0]; sB[u][1] = bp[1];
            sC[u][0] = cp[0]; sC[u][1] = cp[1];
        }
    }
}

// ---------------- gated RMSNorm: y = rmsnorm(ysc * silu(z)) -> fp16 ----------------
__global__ __launch_bounds__(256) void k_gate_rms(
    const float* __restrict__ norm_w, int layer)
{
    int row = blockIdx.x;
    int tid = threadIdx.x;
    int lane = tid & 31, wid = tid >> 5;
    __shared__ float red[8];

    const __half* zrow = g_zxh + (size_t)row*DPROJ;
    size_t base = (size_t)row*DINNER;

    float v0 = __half2float(g_ysc[base + tid])       * siluf(__half2float(zrow[tid]));
    float v1 = __half2float(g_ysc[base + tid + 256]) * siluf(__half2float(zrow[tid + 256]));
    float s = v0*v0 + v1*v1;
#pragma unroll
    for (int o = 16; o > 0; o >>= 1) s += __shfl_xor_sync(0xffffffffu, s, o);
    if (lane == 0) red[wid] = s;
    __syncthreads();
    if (tid < 32) {
        float v = (lane < 8) ? red[lane] : 0.f;
#pragma unroll
        for (int o = 4; o > 0; o >>= 1) v += __shfl_xor_sync(0xffffffffu, v, o);
        if (lane == 0) red[0] = v;
    }
    __syncthreads();
    float scale = rsqrtf(red[0] * (1.f/DINNER) + LN_EPS);
    g_yh[base + tid]       = __float2half_rn(v0 * scale * norm_w[layer*DINNER + tid]);
    g_yh[base + tid + 256] = __float2half_rn(v1 * scale * norm_w[layer*DINNER + tid + 256]);
}

// ---------------- residual + LayerNorm: h = LN(m + h) -> fp32 + fp16 ----------------
__global__ __launch_bounds__(256) void k_res_ln(
    const float* __restrict__ ln_w, const float* __restrict__ ln_b, int layer)
{
    int row = blockIdx.x;
    int tid = threadIdx.x;
    int lane = tid & 31, wid = tid >> 5;
    __shared__ float red1[8], red2[8];

    size_t o = (size_t)row*DMODEL + tid;
    float u = __half2float(g_mh[o]) + g_h[o];
    float s1 = u, s2 = u*u;
#pragma unroll
    for (int ofs = 16; ofs > 0; ofs >>= 1) {
        s1 += __shfl_xor_sync(0xffffffffu, s1, ofs);
        s2 += __shfl_xor_sync(0xffffffffu, s2, ofs);
    }
    if (lane == 0) { red1[wid] = s1; red2[wid] = s2; }
    __syncthreads();
    if (tid < 32) {
        float a = (lane < 8) ? red1[lane] : 0.f;
        float c = (lane < 8) ? red2[lane] : 0.f;
#pragma unroll
        for (int ofs = 4; ofs > 0; ofs >>= 1) {
            a += __shfl_xor_sync(0xffffffffu, a, ofs);
            c += __shfl_xor_sync(0xffffffffu, c, ofs);
        }
        if (lane == 0) { red1[0] = a; red2[0] = c; }
    }
    __syncthreads();
    float mu  = red1[0] * (1.f/DMODEL);
    float var = red2[0] * (1.f/DMODEL) - mu*mu;
    float outv = (u - mu) * rsqrtf(var + LN_EPS) * ln_w[layer*DMODEL + tid]
               + ln_b[layer*DMODEL + tid];
    g_h[o]  = outv;
    g_hh[o] = __float2half_rn(outv);
}

// ---------------- linear_out: out = h @ W[256,5] + b ----------------
__global__ __launch_bounds__(160) void k_linear_out(
    const float* __restrict__ w, const float* __restrict__ bias,
    float* __restrict__ out)
{
    int row = blockIdx.x;
    int tid = threadIdx.x;
    int wid = tid >> 5;
    int lane = tid & 31;
    const float* hr = g_h + (size_t)row*DMODEL;
    float acc = 0.f;
#pragma unroll
    for (int k = lane; k < DMODEL; k += 32) acc += hr[k] * w[k*5 + wid];
#pragma unroll
    for (int o = 16; o > 0; o >>= 1) acc += __shfl_xor_sync(0xffffffffu, acc, o);
    if (lane == 0) out[(size_t)row*5 + wid] = acc + bias[wid];
}

// ---------------- launcher ----------------
extern "C" void kernel_launch(void* const* d_in, const int* in_sizes, int n_in,
                              void* d_out, int out_size)
{
    const float* x         = (const float*)d_in[0];
    const float* lin_in_w  = (const float*)d_in[1];
    const float* lin_in_b  = (const float*)d_in[2];
    const float* W_in      = (const float*)d_in[3];
    const float* conv_w    = (const float*)d_in[4];
    const float* conv_b    = (const float*)d_in[5];
    const float* dt_bias   = (const float*)d_in[6];
    const float* A_log     = (const float*)d_in[7];
    const float* Dp        = (const float*)d_in[8];
    const float* norm_w    = (const float*)d_in[9];
    const float* W_out     = (const float*)d_in[10];
    const float* ln_w      = (const float*)d_in[11];
    const float* ln_b      = (const float*)d_in[12];
    const float* lin_out_w = (const float*)d_in[13];
    const float* lin_out_b = (const float*)d_in[14];
    float* out = (float*)d_out;

    void *ph, *phh, *pzxh, *pmh, *pxh, *pyh;
    cudaGetSymbolAddress(&ph, g_h);
    cudaGetSymbolAddress(&phh, g_hh);
    cudaGetSymbolAddress(&pzxh, g_zxh);
    cudaGetSymbolAddress(&pmh, g_mh);
    cudaGetSymbolAddress(&pxh, g_xh);
    cudaGetSymbolAddress(&pyh, g_yh);
    void *plw, *pwiw, *pwow;
    cudaGetSymbolAddress(&plw, g_linw);
    cudaGetSymbolAddress(&pwiw, g_winw);
    cudaGetSymbolAddress(&pwow, g_woutw);

    static bool attrset = false;
    if (!attrset) {
        cudaFuncSetAttribute(k_gemm_fp16,
            cudaFuncAttributeMaxDynamicSharedMemorySize, GT_SMEM);
        attrset = true;
    }

    // ---- conversions ----
    k_cvt_x<<<NROWS*NCH/256, 256>>>(x, (__half*)pxh);
    k_cvt_w<<<dim3(DMODEL, 1), NCH>>>(lin_in_w, (__half*)plw, NCH, DMODEL, 0, 0);
    k_cvt_w<<<dim3(DPROJP, NLAYERS), DMODEL>>>(W_in, (__half*)pwiw,
        DMODEL, DPROJ, DMODEL*DPROJ, DPROJP*DMODEL);
    k_cvt_w<<<dim3(DMODEL, NLAYERS), DINNER>>>(W_out, (__half*)pwow,
        DINNER, DMODEL, DINNER*DMODEL, DMODEL*DINNER);

    // linear_in: h = x @ lin_in_w + b  (fp32 residual + fp16 copy)
    k_gemm_fp16<<<dim3(2, NROWS/128), 256, GT_SMEM>>>(
        (const __half*)pxh, (const __half*)plw,
        lin_in_b, (float*)ph, (__half*)phh, DMODEL, NCH);

    for (int l = 0; l < NLAYERS; l++) {
        // zxbcdt (fp16 only)
        k_gemm_fp16<<<dim3(DPROJP/128, NROWS/128), 256, GT_SMEM>>>(
            (const __half*)phh,
            (const __half*)pwiw + (size_t)l*DPROJP*DMODEL,
            nullptr, nullptr, (__half*)pzxh, DPROJ, DMODEL);

        k_conv_dt<<<dim3(SEQ/TCH, BATCH), CONVDIM>>>(conv_w, conv_b, dt_bias, A_log, l);

        k_scan<<<BATCH*NHEADS, 512>>>(Dp, l);

        k_gate_rms<<<NROWS, 256>>>(norm_w, l);

        // m = y @ W_out (fp16 only)
        k_gemm_fp16<<<dim3(DMODEL/128, NROWS/128), 256, GT_SMEM>>>(
            (const __half*)pyh,
            (const __half*)pwow + (size_t)l*DMODEL*DINNER,
            nullptr, nullptr, (__half*)pmh, DMODEL, DINNER);

        k_res_ln<<<NROWS, 256>>>(ln_w, ln_b, l);
    }

    k_linear_out<<<NROWS, 160>>>(lin_out_w, lin_out_b, out);
}

// round 9
// speedup vs baseline: 1.2230x; 1.2230x over previous
#include <cuda_runtime.h>
#include <cuda_fp16.h>
#include <cstdint>
#include <math.h>

// ---------------- config ----------------
#define BATCH   16
#define SEQ     2048
#define NCH     64
#define DMODEL  256
#define DINNER  512
#define DSTATE  64
#define NHEADS  8
#define HP      64
#define CONVDIM 640          // DINNER + 2*DSTATE
#define DPROJ   1160         // 2*DINNER + 2*DSTATE + NHEADS
#define NROWS   (BATCH*SEQ)  // 32768
#define NLAYERS 4
#define LN_EPS  1e-5f
#define DPROJP  1280         // DPROJ padded to 128
#define TCH     32           // conv time-chunk

// ---------------- scratch (device globals; allocation-free) ----------------
__device__ float  g_h[NROWS*DMODEL];        // residual stream (fp32)
__device__ __half g_hh[NROWS*DMODEL];       // fp16 copy of h
__device__ __half g_zxh[NROWS*DPROJ];       // zxbcdt (fp16)
__device__ __half g_xacth[NROWS*DINNER];    // silu(conv(x)) (fp16, x part only)
__device__ float  g_bcf[NROWS*2*DSTATE];    // conv'd B,C (fp32)
__device__ float2 g_dtA[NROWS*NHEADS];      // (softplus dt, exp(dt*A)) fp32
__device__ __half g_y0h[NROWS*DINNER];      // scan partial (n 0..31)
__device__ __half g_y1h[NROWS*DINNER];      // scan partial (n 32..63)
__device__ __half g_mh[NROWS*DMODEL];       // y @ W_out (fp16)

// fp16 activations (GEMM A operands)
__device__ __half g_xh[NROWS*NCH];
__device__ __half g_yh[NROWS*DINNER];

// fp16 transposed weights (GEMM B operands), [Npad][K]
__device__ __half g_linw[DMODEL*NCH];
__device__ __half g_winw[NLAYERS*DPROJP*DMODEL];
__device__ __half g_woutw[NLAYERS*DMODEL*DINNER];

__device__ __forceinline__ float siluf(float x) {
    return x * (1.f / (1.f + __expf(-x)));
}

__device__ __forceinline__ uint32_t smem_u32(const void* p) {
    uint32_t a;
    asm("{ .reg .u64 t; cvta.to.shared.u64 t, %1; cvt.u32.u64 %0, t; }"
        : "=r"(a) : "l"(p));
    return a;
}

#define LDM_X4(r0, r1, r2, r3, addr) \
    asm volatile("ldmatrix.sync.aligned.m8n8.x4.shared.b16 {%0,%1,%2,%3}, [%4];" \
        : "=r"(r0), "=r"(r1), "=r"(r2), "=r"(r3) : "r"(addr))

#define MMA_FP16(c, a, b0v, b1v) \
    asm volatile("mma.sync.aligned.m16n8k16.row.col.f32.f16.f16.f32 " \
        "{%0,%1,%2,%3}, {%4,%5,%6,%7}, {%8,%9}, {%0,%1,%2,%3};" \
        : "+f"((c)[0]), "+f"((c)[1]), "+f"((c)[2]), "+f"((c)[3]) \
        : "r"((a)[0]), "r"((a)[1]), "r"((a)[2]), "r"((a)[3]), \
          "r"(b0v), "r"(b1v))

#define CP16(dst, src) \
    asm volatile("cp.async.cg.shared.global [%0], [%1], 16;" \
        :: "r"(dst), "l"(src) : "memory")
#define CPCOMMIT() asm volatile("cp.async.commit_group;" ::: "memory")
#define CPWAIT(n)  asm volatile("cp.async.wait_group %0;" :: "n"(n) : "memory")

// ---------------- weight / input conversion ----------------
__global__ void k_cvt_w(const float* __restrict__ src, __half* __restrict__ dh,
                        int K, int N, int srcStrideLayer, int dstStrideLayer)
{
    int n = blockIdx.x;
    int l = blockIdx.y;
    int k = threadIdx.x;                 // blockDim.x == K
    float v = (n < N) ? src[(size_t)l*srcStrideLayer + (size_t)k*N + n] : 0.f;
    dh[(size_t)l*dstStrideLayer + (size_t)n*K + k] = __float2half_rn(v);
}

__global__ void k_cvt_x(const float* __restrict__ src, __half* __restrict__ d)
{
    int i = blockIdx.x * 256 + threadIdx.x;
    d[i] = __float2half_rn(src[i]);
}

// ============================================================================
// Single-pass fp16 tensor-core GEMM (proven round-6/7 version)
// ============================================================================
#define GSTRIDE 40
#define TILEB   (128*GSTRIDE*2)
#define STAGEB  (2*TILEB)
#define GT_SMEM (2*STAGEB)

__global__ __launch_bounds__(256, 2) void k_gemm_fp16(
    const __half* __restrict__ A, const __half* __restrict__ B,
    const float* __restrict__ bias, float* __restrict__ C,
    __half* __restrict__ Ch, int N, int K)
{
    extern __shared__ __align__(128) uint8_t dsm[];
    const uint32_t smb = smem_u32(dsm);

    int tid = threadIdx.x;
    int wid = tid >> 5, lane = tid & 31;
    int m0 = blockIdx.y * 128, n0 = blockIdx.x * 128;
    int wm = wid & 3, wn = wid >> 2;

    float acc[2][8][4];
#pragma unroll
    for (int mt = 0; mt < 2; mt++)
#pragma unroll
        for (int nt = 0; nt < 8; nt++)
#pragma unroll
            for (int j = 0; j < 4; j++) acc[mt][nt][j] = 0.f;

    const __half* srcs[2] = { A + (size_t)m0 * K, B + (size_t)n0 * K };
    const int row0 = tid >> 2, part = tid & 3;

    const uint32_t aoff = (uint32_t)((wm*32 + (lane & 7) + ((lane >> 3) & 1) * 8) * (GSTRIDE*2))
                        + ((lane >> 4) & 1) * 16;
    const uint32_t boff = (uint32_t)((wn*64 + (lane & 7) + ((lane >> 4) & 1) * 8) * (GSTRIDE*2))
                        + ((lane >> 3) & 1) * 16;

    const int NC = K >> 5;

#pragma unroll
    for (int t = 0; t < 2; t++) {
#pragma unroll
        for (int it = 0; it < 2; it++) {
            int r = row0 + it * 64;
            uint32_t d = smb + t * TILEB + (uint32_t)(r * (GSTRIDE*2) + part * 16);
            CP16(d, srcs[t] + (size_t)r * K + part * 8);
        }
    }
    CPCOMMIT();

    for (int c = 0; c < NC; c++) {
        int s = c & 1;
        if (c + 1 < NC) {
            uint32_t sb2 = smb + ((c + 1) & 1) * STAGEB;
            int kb = (c + 1) * 32;
#pragma unroll
            for (int t = 0; t < 2; t++) {
#pragma unroll
                for (int it = 0; it < 2; it++) {
                    int r = row0 + it * 64;
                    uint32_t d = sb2 + t * TILEB + (uint32_t)(r * (GSTRIDE*2) + part * 16);
                    CP16(d, srcs[t] + (size_t)r * K + kb + part * 8);
                }
            }
            CPCOMMIT();
            CPWAIT(1);
        } else {
            CPWAIT(0);
        }
        __syncthreads();

        uint32_t sbase = smb + s * STAGEB;
#pragma unroll
        for (int ks = 0; ks < 2; ks++) {
            uint32_t abase = sbase + aoff + ks * 32;
            uint32_t ra[2][4];
            LDM_X4(ra[0][0], ra[0][1], ra[0][2], ra[0][3], abase);
            LDM_X4(ra[1][0], ra[1][1], ra[1][2], ra[1][3],
                   abase + 16 * (GSTRIDE*2));
            uint32_t rb[8][2];
            uint32_t bbase = sbase + TILEB + boff + ks * 32;
#pragma unroll
            for (int g = 0; g < 4; g++)
                LDM_X4(rb[2*g][0], rb[2*g][1], rb[2*g+1][0], rb[2*g+1][1],
                       bbase + g * 16 * (GSTRIDE*2));
#pragma unroll
            for (int mt = 0; mt < 2; mt++)
#pragma unroll
                for (int nt = 0; nt < 8; nt++)
                    MMA_FP16(acc[mt][nt], ra[mt], rb[nt][0], rb[nt][1]);
        }
        __syncthreads();
    }

    const int gid = lane >> 2, tig = lane & 3;
#pragma unroll
    for (int mt = 0; mt < 2; mt++) {
#pragma unroll
        for (int nt = 0; nt < 8; nt++) {
            int col = n0 + wn * 64 + nt * 8 + tig * 2;
            if (col < N) {
                int r0 = m0 + wm * 32 + mt * 16 + gid;
                float2 v0 = make_float2(acc[mt][nt][0], acc[mt][nt][1]);
                float2 v1 = make_float2(acc[mt][nt][2], acc[mt][nt][3]);
                if (bias) {
                    float b0 = bias[col], b1 = bias[col + 1];
                    v0.x += b0; v0.y += b1; v1.x += b0; v1.y += b1;
                }
                if (C) {
                    *(float2*)(C + (size_t)r0 * N + col) = v0;
                    *(float2*)(C + (size_t)(r0 + 8) * N + col) = v1;
                }
                if (Ch) {
                    *(__half2*)(Ch + (size_t)r0 * N + col) =
                        __floats2half2_rn(v0.x, v0.y);
                    *(__half2*)(Ch + (size_t)(r0 + 8) * N + col) =
                        __floats2half2_rn(v1.x, v1.y);
                }
            }
        }
    }
}

// ------------- causal depthwise conv(4) + SiLU + dt/dA, t-chunked -------------
// x channels (0..511) -> g_xacth fp16; B/C channels (512..639) -> g_bcf fp32.
__global__ __launch_bounds__(CONVDIM) void k_conv_dt(
    const float* __restrict__ conv_w, const float* __restrict__ conv_b,
    const float* __restrict__ dt_bias, const float* __restrict__ A_log,
    int layer)
{
    int t0 = blockIdx.x * TCH;
    int b  = blockIdx.y;
    int c  = threadIdx.x;                  // 0..639

    const float* wr = conv_w + (size_t)layer*CONVDIM*4 + c*4;
    float w0 = wr[0], w1 = wr[1], w2 = wr[2], w3 = wr[3];
    float cb = conv_b[layer*CONVDIM + c];

    const __half* zc = g_zxh + (size_t)(b*SEQ)*DPROJ + DINNER + c;
    float h3 = 0.f, h2 = 0.f, h1 = 0.f;
    if (t0 >= 3) {
        h3 = __half2float(zc[(size_t)(t0-3)*DPROJ]);
        h2 = __half2float(zc[(size_t)(t0-2)*DPROJ]);
        h1 = __half2float(zc[(size_t)(t0-1)*DPROJ]);
    }

    float dtb = 0.f, Aneg = 0.f;
    const __half* dz = nullptr;
    if (c < NHEADS) {
        dtb  = dt_bias[layer*NHEADS + c];
        Aneg = -expf(A_log[layer*NHEADS + c]);
        dz   = g_zxh + (size_t)(b*SEQ)*DPROJ + DINNER + CONVDIM + c;
    }

    bool isx = (c < DINNER);
    __half* xo = g_xacth + (size_t)(b*SEQ + t0)*DINNER + c;
    float*  bo = g_bcf   + (size_t)(b*SEQ + t0)*(2*DSTATE) + (c - DINNER);

#pragma unroll 4
    for (int u = 0; u < TCH; u++) {
        float cur = __half2float(zc[(size_t)(t0+u)*DPROJ]);
        float s = cb + h3*w0 + h2*w1 + h1*w2 + cur*w3;
        float act = siluf(s);
        if (isx) xo[(size_t)u*DINNER] = __float2half_rn(act);
        else     bo[(size_t)u*(2*DSTATE)] = act;
        h3 = h2; h2 = h1; h1 = cur;
        if (c < NHEADS) {
            float draw = __half2float(dz[(size_t)(t0+u)*DPROJ]) + dtb;
            float dtv = (draw > 20.f) ? draw : log1pf(expf(draw));
            g_dtA[(size_t)(b*SEQ + t0 + u)*NHEADS + c] =
                make_float2(dtv, expf(dtv * Aneg));
        }
    }
}

// ---------------- sequential selective scan (round-7 structure, fp32 B/C) ----
// grid = 256 (bh * 2 halves), block 256: p = tid>>2, q = tid&3,
// n-slice = half*32 + q*8 (8 fp32 states/thread). 4-deep register prefetch.
// B/C read as float4 from g_bcf (no cvt). Partials -> g_y0h / g_y1h (fp16).
__global__ __launch_bounds__(256) void k_scan(
    const float* __restrict__ Dp, int layer)
{
    int bh = blockIdx.x >> 1, half = blockIdx.x & 1;
    int b = bh >> 3, h = bh & 7;
    int tid = threadIdx.x;
    int p = tid >> 2, q = tid & 3;
    int n0 = half*32 + q*8;

    float S[8];
#pragma unroll
    for (int j = 0; j < 8; j++) S[j] = 0.f;

    float Dh = (half == 0) ? Dp[layer*NHEADS + h] : 0.f;

    const __half*  xrow = g_xacth + (size_t)(b*SEQ)*DINNER + h*HP + p;
    const float2*  dap  = g_dtA   + (size_t)(b*SEQ)*NHEADS + h;
    const float*   bcb  = g_bcf   + (size_t)(b*SEQ)*(2*DSTATE);
    __half* yp = (half == 0 ? g_y0h : g_y1h)
               + (size_t)(b*SEQ)*DINNER + h*HP + p;

    float sx[4]; float2 sda[4];
    float sB[4][8], sC[4][8];
#pragma unroll
    for (int u = 0; u < 4; u++) {
        sx[u]  = __half2float(xrow[(size_t)u*DINNER]);
        sda[u] = dap[u*NHEADS];
        const float* bc = bcb + (size_t)u*(2*DSTATE);
        ((float4*)sB[u])[0] = *(const float4*)(bc + n0);
        ((float4*)sB[u])[1] = *(const float4*)(bc + n0 + 4);
        ((float4*)sC[u])[0] = *(const float4*)(bc + DSTATE + n0);
        ((float4*)sC[u])[1] = *(const float4*)(bc + DSTATE + n0 + 4);
    }

    for (int t = 0; t < SEQ; t += 4) {
#pragma unroll
        for (int u = 0; u < 4; u++) {
            float xv = sx[u];
            float2 da = sda[u];
            float coef = da.x * xv;
            float a0 = 0.f, a1 = 0.f;
#pragma unroll
            for (int j = 0; j < 4; j++) {
                S[j] = S[j]*da.y + coef*sB[u][j];
                a0 += S[j]*sC[u][j];
            }
#pragma unroll
            for (int j = 4; j < 8; j++) {
                S[j] = S[j]*da.y + coef*sB[u][j];
                a1 += S[j]*sC[u][j];
            }
            float acc = a0 + a1;
            acc += __shfl_xor_sync(0xffffffffu, acc, 1);
            acc += __shfl_xor_sync(0xffffffffu, acc, 2);
            if (q == 0)
                yp[(size_t)(t+u)*DINNER] = __float2half_rn(acc + Dh*xv);

            int tt = t + u + 4; if (tt > SEQ - 1) tt = SEQ - 1;
            sx[u]  = __half2float(xrow[(size_t)tt*DINNER]);
            sda[u] = dap[tt*NHEADS];
            const float* bc = bcb + (size_t)tt*(2*DSTATE);
            ((float4*)sB[u])[0] = *(const float4*)(bc + n0);
            ((float4*)sB[u])[1] = *(const float4*)(bc + n0 + 4);
            ((float4*)sC[u])[0] = *(const float4*)(bc + DSTATE + n0);
            ((float4*)sC[u])[1] = *(const float4*)(bc + DSTATE + n0 + 4);
        }
    }
}

// ---------------- gated RMSNorm: y = rmsnorm((y0+y1) * silu(z)) -> fp16 ----------------
__global__ __launch_bounds__(256) void k_gate_rms(
    const float* __restrict__ norm_w, int layer)
{
    int row = blockIdx.x;
    int tid = threadIdx.x;
    int lane = tid & 31, wid = tid >> 5;
    __shared__ float red[8];

    const __half* zrow = g_zxh + (size_t)row*DPROJ;
    size_t base = (size_t)row*DINNER;

    float y0a = __half2float(g_y0h[base + tid])       + __half2float(g_y1h[base + tid]);
    float y1a = __half2float(g_y0h[base + tid + 256]) + __half2float(g_y1h[base + tid + 256]);
    float v0 = y0a * siluf(__half2float(zrow[tid]));
    float v1 = y1a * siluf(__half2float(zrow[tid + 256]));
    float s = v0*v0 + v1*v1;
#pragma unroll
    for (int o = 16; o > 0; o >>= 1) s += __shfl_xor_sync(0xffffffffu, s, o);
    if (lane == 0) red[wid] = s;
    __syncthreads();
    if (tid < 32) {
        float v = (lane < 8) ? red[lane] : 0.f;
#pragma unroll
        for (int o = 4; o > 0; o >>= 1) v += __shfl_xor_sync(0xffffffffu, v, o);
        if (lane == 0) red[0] = v;
    }
    __syncthreads();
    float scale = rsqrtf(red[0] * (1.f/DINNER) + LN_EPS);
    g_yh[base + tid]       = __float2half_rn(v0 * scale * norm_w[layer*DINNER + tid]);
    g_yh[base + tid + 256] = __float2half_rn(v1 * scale * norm_w[layer*DINNER + tid + 256]);
}

// ---------------- residual + LayerNorm: h = LN(m + h) -> fp32 + fp16 ----------------
__global__ __launch_bounds__(256) void k_res_ln(
    const float* __restrict__ ln_w, const float* __restrict__ ln_b, int layer)
{
    int row = blockIdx.x;
    int tid = threadIdx.x;
    int lane = tid & 31, wid = tid >> 5;
    __shared__ float red1[8], red2[8];

    size_t o = (size_t)row*DMODEL + tid;
    float u = __half2float(g_mh[o]) + g_h[o];
    float s1 = u, s2 = u*u;
#pragma unroll
    for (int ofs = 16; ofs > 0; ofs >>= 1) {
        s1 += __shfl_xor_sync(0xffffffffu, s1, ofs);
        s2 += __shfl_xor_sync(0xffffffffu, s2, ofs);
    }
    if (lane == 0) { red1[wid] = s1; red2[wid] = s2; }
    __syncthreads();
    if (tid < 32) {
        float a = (lane < 8) ? red1[lane] : 0.f;
        float c = (lane < 8) ? red2[lane] : 0.f;
#pragma unroll
        for (int ofs = 4; ofs > 0; ofs >>= 1) {
            a += __shfl_xor_sync(0xffffffffu, a, ofs);
            c += __shfl_xor_sync(0xffffffffu, c, ofs);
        }
        if (lane == 0) { red1[0] = a; red2[0] = c; }
    }
    __syncthreads();
    float mu  = red1[0] * (1.f/DMODEL);
    float var = red2[0] * (1.f/DMODEL) - mu*mu;
    float outv = (u - mu) * rsqrtf(var + LN_EPS) * ln_w[layer*DMODEL + tid]
               + ln_b[layer*DMODEL + tid];
    g_h[o]  = outv;
    g_hh[o] = __float2half_rn(outv);
}

// ---------------- linear_out: out = h @ W[256,5] + b ----------------
__global__ __launch_bounds__(160) void k_linear_out(
    const float* __restrict__ w, const float* __restrict__ bias,
    float* __restrict__ out)
{
    int row = blockIdx.x;
    int tid = threadIdx.x;
    int wid = tid >> 5;
    int lane = tid & 31;
    const float* hr = g_h + (size_t)row*DMODEL;
    float acc = 0.f;
#pragma unroll
    for (int k = lane; k < DMODEL; k += 32) acc += hr[k] * w[k*5 + wid];
#pragma unroll
    for (int o = 16; o > 0; o >>= 1) acc += __shfl_xor_sync(0xffffffffu, acc, o);
    if (lane == 0) out[(size_t)row*5 + wid] = acc + bias[wid];
}

// ---------------- launcher ----------------
extern "C" void kernel_launch(void* const* d_in, const int* in_sizes, int n_in,
                              void* d_out, int out_size)
{
    const float* x         = (const float*)d_in[0];
    const float* lin_in_w  = (const float*)d_in[1];
    const float* lin_in_b  = (const float*)d_in[2];
    const float* W_in      = (const float*)d_in[3];
    const float* conv_w    = (const float*)d_in[4];
    const float* conv_b    = (const float*)d_in[5];
    const float* dt_bias   = (const float*)d_in[6];
    const float* A_log     = (const float*)d_in[7];
    const float* Dp        = (const float*)d_in[8];
    const float* norm_w    = (const float*)d_in[9];
    const float* W_out     = (const float*)d_in[10];
    const float* ln_w      = (const float*)d_in[11];
    const float* ln_b      = (const float*)d_in[12];
    const float* lin_out_w = (const float*)d_in[13];
    const float* lin_out_b = (const float*)d_in[14];
    float* out = (float*)d_out;

    void *ph, *phh, *pzxh, *pmh, *pxh, *pyh;
    cudaGetSymbolAddress(&ph, g_h);
    cudaGetSymbolAddress(&phh, g_hh);
    cudaGetSymbolAddress(&pzxh, g_zxh);
    cudaGetSymbolAddress(&pmh, g_mh);
    cudaGetSymbolAddress(&pxh, g_xh);
    cudaGetSymbolAddress(&pyh, g_yh);
    void *plw, *pwiw, *pwow;
    cudaGetSymbolAddress(&plw, g_linw);
    cudaGetSymbolAddress(&pwiw, g_winw);
    cudaGetSymbolAddress(&pwow, g_woutw);

    static bool attrset = false;
    if (!attrset) {
        cudaFuncSetAttribute(k_gemm_fp16,
            cudaFuncAttributeMaxDynamicSharedMemorySize, GT_SMEM);
        attrset = true;
    }

    // ---- conversions ----
    k_cvt_x<<<NROWS*NCH/256, 256>>>(x, (__half*)pxh);
    k_cvt_w<<<dim3(DMODEL, 1), NCH>>>(lin_in_w, (__half*)plw, NCH, DMODEL, 0, 0);
    k_cvt_w<<<dim3(DPROJP, NLAYERS), DMODEL>>>(W_in, (__half*)pwiw,
        DMODEL, DPROJ, DMODEL*DPROJ, DPROJP*DMODEL);
    k_cvt_w<<<dim3(DMODEL, NLAYERS), DINNER>>>(W_out, (__half*)pwow,
        DINNER, DMODEL, DINNER*DMODEL, DMODEL*DINNER);

    // linear_in: h = x @ lin_in_w + b  (fp32 residual + fp16 copy)
    k_gemm_fp16<<<dim3(2, NROWS/128), 256, GT_SMEM>>>(
        (const __half*)pxh, (const __half*)plw,
        lin_in_b, (float*)ph, (__half*)phh, DMODEL, NCH);

    for (int l = 0; l < NLAYERS; l++) {
        // zxbcdt (fp16 only)
        k_gemm_fp16<<<dim3(DPROJP/128, NROWS/128), 256, GT_SMEM>>>(
            (const __half*)phh,
            (const __half*)pwiw + (size_t)l*DPROJP*DMODEL,
            nullptr, nullptr, (__half*)pzxh, DPROJ, DMODEL);

        k_conv_dt<<<dim3(SEQ/TCH, BATCH), CONVDIM>>>(conv_w, conv_b, dt_bias, A_log, l);

        k_scan<<<BATCH*NHEADS*2, 256>>>(Dp, l);

        k_gate_rms<<<NROWS, 256>>>(norm_w, l);

        // m = y @ W_out (fp16 only)
        k_gemm_fp16<<<dim3(DMODEL/128, NROWS/128), 256, GT_SMEM>>>(
            (const __half*)pyh,
            (const __half*)pwow + (size_t)l*DMODEL*DINNER,
            nullptr, nullptr, (__half*)pmh, DMODEL, DINNER);

        k_res_ln<<<NROWS, 256>>>(ln_w, ln_b, l);
    }

    k_linear_out<<<NROWS, 160>>>(lin_out_w, lin_out_b, out);
}